// round 14
// baseline (speedup 1.0000x reference)
#include <cuda_runtime.h>
#include <cuda_bf16.h>
#include <cstdint>

#define NTOK 9216        // H*W = 96*96
#define BATCH 2
#define CH 64
#define ID 32            // inter dim
#define BOTT 16
#define NSPLIT 4
#define NJ (NTOK / 64 / NSPLIT)   // 36 KV tiles per split

// ---------------- device scratch ----------------
__device__ __align__(16) __nv_bfloat16 d_thetaQ[BATCH * NTOK * ID]; // [B][N][32], pre-scaled
__device__ __align__(16) __nv_bfloat16 d_phiK  [BATCH * NTOK * ID]; // [B][N][32]
__device__ __align__(16) __nv_bfloat16 d_gxT   [BATCH * ID * NTOK]; // [B][32][N]
__device__ __align__(16) __nv_bfloat16 d_Opart[NSPLIT * BATCH * NTOK * ID]; // partial O (bf16)
__device__ float d_lpart[NSPLIT * BATCH * NTOK];                    // partial softmax denom
__device__ float d_pooled[BATCH * CH];

// ---------------- helpers ----------------
// packed bf16x2 cubic fit of 2^x on [-1,1]; bf16 rounding error is common-mode
// between P (numerator) and the HADD2-tree denominator -> largely cancels.
#define C3_BF16X2 0x3D6A3D6Au   // 0.05717
#define C2_BF16X2 0x3E803E80u   // 0.25
#define C1_BF16X2 0x3F313F31u   // 0.69141
#define C0_BF16X2 0x3F803F80u   // 1.0
__device__ __forceinline__ uint32_t exp2_poly_bf16x2(uint32_t x) {
    uint32_t p;
    asm("fma.rn.bf16x2 %0, %1, %2, %3;" : "=r"(p) : "r"(x), "r"(C3_BF16X2), "r"(C2_BF16X2));
    asm("fma.rn.bf16x2 %0, %1, %2, %3;" : "=r"(p) : "r"(p), "r"(x), "r"(C1_BF16X2));
    asm("fma.rn.bf16x2 %0, %1, %2, %3;" : "=r"(p) : "r"(p), "r"(x), "r"(C0_BF16X2));
    return p;
}
__device__ __forceinline__ uint32_t hadd2(uint32_t a, uint32_t b) {
    uint32_t d; asm("add.rn.bf16x2 %0, %1, %2;" : "=r"(d) : "r"(a), "r"(b)); return d;
}
__device__ __forceinline__ float bf16x2_hsum(uint32_t v) {
    __nv_bfloat162 h = *reinterpret_cast<__nv_bfloat162*>(&v);
    return __low2float(h) + __high2float(h);
}
__device__ __forceinline__ uint32_t pack_bf16(float lo, float hi) {
    uint32_t d; asm("cvt.rn.bf16x2.f32 %0, %1, %2;" : "=r"(d) : "f"(hi), "f"(lo)); return d;
}
__device__ __forceinline__ void mma_bf16(float c[4], const uint32_t a[4], uint32_t b0, uint32_t b1) {
    asm volatile(
        "mma.sync.aligned.m16n8k16.row.col.f32.bf16.bf16.f32 "
        "{%0,%1,%2,%3}, {%4,%5,%6,%7}, {%8,%9}, {%0,%1,%2,%3};"
        : "+f"(c[0]), "+f"(c[1]), "+f"(c[2]), "+f"(c[3])
        : "r"(a[0]), "r"(a[1]), "r"(a[2]), "r"(a[3]), "r"(b0), "r"(b1));
}
__device__ __forceinline__ void ldmx4(uint32_t r[4], const __nv_bfloat16* p) {
    uint32_t a = (uint32_t)__cvta_generic_to_shared(p);
    asm volatile("ldmatrix.sync.aligned.m8n8.x4.shared.b16 {%0,%1,%2,%3}, [%4];"
                 : "=r"(r[0]), "=r"(r[1]), "=r"(r[2]), "=r"(r[3]) : "r"(a));
}
__device__ __forceinline__ void cp16(void* smem, const void* gmem) {
    uint32_t s = (uint32_t)__cvta_generic_to_shared(smem);
    asm volatile("cp.async.cg.shared.global [%0], [%1], 16;" :: "r"(s), "l"(gmem));
}
#define CP_COMMIT() asm volatile("cp.async.commit_group;")
#define CP_WAIT0()  asm volatile("cp.async.wait_group 0;")

// ---------------- 1) global average pool ----------------
__global__ void pool_kernel(const float* __restrict__ x) {
    int bc = blockIdx.x;
    const float* p = x + (size_t)bc * NTOK;
    float s = 0.f;
    for (int i = threadIdx.x; i < NTOK; i += 256) s += p[i];
    __shared__ float red[8];
    #pragma unroll
    for (int o = 16; o; o >>= 1) s += __shfl_xor_sync(~0u, s, o);
    if ((threadIdx.x & 31) == 0) red[threadIdx.x >> 5] = s;
    __syncthreads();
    if (threadIdx.x < 8) {
        float v = red[threadIdx.x];
        #pragma unroll
        for (int o = 4; o; o >>= 1) v += __shfl_xor_sync(0xffu, v, o);
        if (threadIdx.x == 0) d_pooled[bc] = v * (1.f / (float)NTOK);
    }
}

// ---------------- 2) projections ----------------
// 512 threads = 4 i-groups x 128 tokens; each thread computes 8 of 32 outputs.
__global__ __launch_bounds__(512) void proj_kernel(const float* __restrict__ x,
                            const float* __restrict__ g_w,
                            const float* __restrict__ theta_w,
                            const float* __restrict__ phi_w) {
    __shared__ float sg[ID * CH], st[ID * CH], sp[ID * CH];
    const int b   = blockIdx.y;
    const int tid = threadIdx.x;
    const int n   = blockIdx.x * 128 + (tid & 127);
    const int ig  = tid >> 7;              // 0..3 -> outputs ig*8 .. ig*8+7
    for (int i = tid; i < ID * CH; i += 512) {
        sg[i] = g_w[i]; st[i] = theta_w[i]; sp[i] = phi_w[i];
    }
    __syncthreads();

    float xv[CH];
    const float* xb = x + (size_t)b * CH * NTOK + n;
    #pragma unroll
    for (int c = 0; c < CH; c++) xv[c] = xb[(size_t)c * NTOK];

    const float qscale = (1.0f / 1.5f) * 1.4426950408889634f; // 1/T * log2(e)

    __nv_bfloat16 tqv[8], pkv[8];
    __nv_bfloat16* gv = d_gxT + (size_t)b * ID * NTOK + n;

    #pragma unroll
    for (int ii = 0; ii < 8; ii++) {
        const int i = ig * 8 + ii;
        float ag = 0.f, at = 0.f, ap = 0.f;
        const float* wg = &sg[i * CH];
        const float* wt = &st[i * CH];
        const float* wp = &sp[i * CH];
        #pragma unroll
        for (int c = 0; c < CH; c++) {
            float xc = xv[c];
            ag = fmaf(wg[c], xc, ag);
            at = fmaf(wt[c], xc, at);
            ap = fmaf(wp[c], xc, ap);
        }
        tqv[ii] = __float2bfloat16(at * qscale);
        pkv[ii] = __float2bfloat16(ap);
        gv[(size_t)i * NTOK] = __float2bfloat16(ag);
    }
    *(uint4*)&d_thetaQ[((size_t)b * NTOK + n) * ID + ig * 8] = *(const uint4*)tqv;
    *(uint4*)&d_phiK  [((size_t)b * NTOK + n) * ID + ig * 8] = *(const uint4*)pkv;
}

// ---------------- 3) flash attention (R8-proven structure) ----------------
// BM=128 (4 warps x 32 rows), BN=64, D=32, KV-split=4, 4 CTAs/SM.
__global__ __launch_bounds__(128, 4) void attn_kernel() {
    const int by    = blockIdx.y;
    const int b     = by / NSPLIT;
    const int split = by % NSPLIT;
    const int j0    = split * NJ;
    const int m0    = blockIdx.x * 128;
    const int tid   = threadIdx.x;
    const int warp  = tid >> 5, lane = tid & 31;
    const int g = lane >> 2, t = lane & 3;
    const int lr = lane & 7, lm = lane >> 3;   // ldmatrix row / matrix-id

    __shared__ __align__(16) __nv_bfloat16 sQ[128][40];
    __shared__ __align__(16) __nv_bfloat16 sK[2][64][40];
    __shared__ __align__(16) __nv_bfloat16 sV[2][32][72];

    const __nv_bfloat16* Qg = d_thetaQ + (size_t)b * NTOK * ID;
    const __nv_bfloat16* Kg = d_phiK   + (size_t)b * NTOK * ID;
    const __nv_bfloat16* Vg = d_gxT    + (size_t)b * ID * NTOK;

    // async-load Q tile [128][32]
    {
        int idx = tid;
        #pragma unroll
        for (int u = 0; u < 4; u++, idx += 128) {
            int r = idx >> 2, c = (idx & 3) * 8;
            cp16(&sQ[r][c], &Qg[(size_t)(m0 + r) * ID + c]);
        }
    }
    // prefetch first K/V tile into buffer 0
    {
        int idx = tid;
        #pragma unroll
        for (int u = 0; u < 2; u++, idx += 128) {
            int r = idx >> 2, c = (idx & 3) * 8;
            cp16(&sK[0][r][c], &Kg[(size_t)(j0 * 64 + r) * ID + c]);
        }
        idx = tid;
        #pragma unroll
        for (int u = 0; u < 2; u++, idx += 128) {
            int r = idx >> 3, c = (idx & 7) * 8;
            cp16(&sV[0][r][c], &Vg[(size_t)r * NTOK + j0 * 64 + c]);
        }
    }
    CP_COMMIT();

    uint32_t qa[2][2][4];      // [m-tile][k-step]
    bool qa_loaded = false;

    float o[2][4][4] = {};     // output d-tiles
    float lacc[2][2] = {};     // per-thread partial softmax denom [mt][row]

    for (int jl = 0; jl < NJ; jl++) {
        const int cur = jl & 1;
        CP_WAIT0();
        __syncthreads();

        if (!qa_loaded) {
            qa_loaded = true;
            #pragma unroll
            for (int mt = 0; mt < 2; mt++)
                #pragma unroll
                for (int ks = 0; ks < 2; ks++)
                    ldmx4(qa[mt][ks],
                          &sQ[warp * 32 + mt * 16 + (lm & 1) * 8 + lr][ks * 16 + (lm >> 1) * 8]);
        }

        // prefetch next tile
        if (jl + 1 < NJ) {
            const int jj = j0 + jl + 1, nb = cur ^ 1;
            int idx = tid;
            #pragma unroll
            for (int u = 0; u < 2; u++, idx += 128) {
                int r = idx >> 2, c = (idx & 3) * 8;
                cp16(&sK[nb][r][c], &Kg[(size_t)(jj * 64 + r) * ID + c]);
            }
            idx = tid;
            #pragma unroll
            for (int u = 0; u < 2; u++, idx += 128) {
                int r = idx >> 3, c = (idx & 7) * 8;
                cp16(&sV[nb][r][c], &Vg[(size_t)r * NTOK + jj * 64 + c]);
            }
        }
        CP_COMMIT();

        // S = Q K^T ; pack logits to bf16x2 per u-tile
        uint32_t pp[2][8][2];
        #pragma unroll
        for (int u = 0; u < 8; u++) {
            uint32_t kb[4];
            ldmx4(kb, &sK[cur][u * 8 + lr][lm * 8]);
            #pragma unroll
            for (int mt = 0; mt < 2; mt++) {
                float s0[4] = {0.f, 0.f, 0.f, 0.f};
                mma_bf16(s0, qa[mt][0], kb[0], kb[1]);
                mma_bf16(s0, qa[mt][1], kb[2], kb[3]);
                pp[mt][u][0] = pack_bf16(s0[0], s0[1]);   // row g
                pp[mt][u][1] = pack_bf16(s0[2], s0[3]);   // row g+8
            }
        }

        // P = 2^S in packed bf16x2
        #pragma unroll
        for (int mt = 0; mt < 2; mt++)
            #pragma unroll
            for (int u = 0; u < 8; u++) {
                pp[mt][u][0] = exp2_poly_bf16x2(pp[mt][u][0]);
                pp[mt][u][1] = exp2_poly_bf16x2(pp[mt][u][1]);
            }

        // denominator: HADD2 tree over packed P, accumulate in f32 per thread
        #pragma unroll
        for (int mt = 0; mt < 2; mt++) {
            #pragma unroll
            for (int r = 0; r < 2; r++) {
                uint32_t a0 = hadd2(pp[mt][0][r], pp[mt][1][r]);
                uint32_t a1 = hadd2(pp[mt][2][r], pp[mt][3][r]);
                uint32_t a2 = hadd2(pp[mt][4][r], pp[mt][5][r]);
                uint32_t a3 = hadd2(pp[mt][6][r], pp[mt][7][r]);
                uint32_t b0 = hadd2(a0, a1);
                uint32_t b1 = hadd2(a2, a3);
                lacc[mt][r] += bf16x2_hsum(b0) + bf16x2_hsum(b1);
            }
        }

        // O += P V
        #pragma unroll
        for (int kk = 0; kk < 4; kk++) {
            #pragma unroll
            for (int dp = 0; dp < 2; dp++) {
                uint32_t vb[4];
                ldmx4(vb, &sV[cur][(dp * 2 + (lm >> 1)) * 8 + lr][kk * 16 + (lm & 1) * 8]);
                #pragma unroll
                for (int mt = 0; mt < 2; mt++) {
                    uint32_t pa[4] = {pp[mt][2 * kk][0], pp[mt][2 * kk][1],
                                      pp[mt][2 * kk + 1][0], pp[mt][2 * kk + 1][1]};
                    mma_bf16(o[mt][dp * 2    ], pa, vb[0], vb[1]);
                    mma_bf16(o[mt][dp * 2 + 1], pa, vb[2], vb[3]);
                }
            }
        }
    }

    // reduce l across the 4 lanes of each row-quad (once)
    #pragma unroll
    for (int mt = 0; mt < 2; mt++)
        #pragma unroll
        for (int r = 0; r < 2; r++) {
            lacc[mt][r] += __shfl_xor_sync(~0u, lacc[mt][r], 1);
            lacc[mt][r] += __shfl_xor_sync(~0u, lacc[mt][r], 2);
        }

    const size_t pbase = (size_t)(split * BATCH + b) * NTOK;
    __nv_bfloat16* Op = d_Opart + pbase * ID;
    #pragma unroll
    for (int mt = 0; mt < 2; mt++) {
        int r0 = m0 + warp * 32 + mt * 16 + g;
        if (t == 0) {
            d_lpart[pbase + r0]     = lacc[mt][0];
            d_lpart[pbase + r0 + 8] = lacc[mt][1];
        }
        #pragma unroll
        for (int dt = 0; dt < 4; dt++) {
            int c = dt * 8 + 2 * t;
            *(uint32_t*)&Op[(size_t)r0 * ID + c]       = pack_bf16(o[mt][dt][0], o[mt][dt][1]);
            *(uint32_t*)&Op[(size_t)(r0 + 8) * ID + c] = pack_bf16(o[mt][dt][2], o[mt][dt][3]);
        }
    }
}

// ---------------- 4) epilogue: gate MLP + combine splits + out ----------------
// 256 threads, 16 tokens/block (grid 1152): 16 channel-groups x 16 tokens,
// only 4 channels per thread -> short dependent chains.
__global__ __launch_bounds__(256) void epi_kernel(const float* __restrict__ x, const float* __restrict__ W_w,
                           const float* __restrict__ cg1_w, const float* __restrict__ cg1_b,
                           const float* __restrict__ cg2_w, const float* __restrict__ cg2_b,
                           float* __restrict__ out) {
    __shared__ float sw[CH * ID];
    __shared__ float sov[16][33];     // odd pitch: conflict-free column reads
    __shared__ float sinv[16];
    __shared__ float sh[BOTT];
    __shared__ float sgate[CH];
    const int b   = blockIdx.y;
    const int n0  = blockIdx.x * 16;
    const int tid = threadIdx.x;

    for (int i = tid; i < CH * ID; i += 256) sw[i] = W_w[i];
    if (tid < BOTT) {
        float acc = cg1_b[tid];
        #pragma unroll
        for (int c = 0; c < CH; c++) acc = fmaf(d_pooled[b * CH + c], cg1_w[tid * CH + c], acc);
        sh[tid] = fmaxf(acc, 0.f);
    }
    __syncthreads();
    if (tid < CH) {
        float acc = cg2_b[tid];
        #pragma unroll
        for (int k = 0; k < BOTT; k++) acc = fmaf(sh[k], cg2_w[tid * BOTT + k], acc);
        sgate[tid] = 0.8f / (1.f + __expf(-acc));
    }
    // combine splits: 16 tokens x 8 dim-quads = 128 work items (bf16 loads)
    if (tid < 128) {
        const int tok = tid >> 3, d4 = (tid & 7) * 4;
        float a0 = 0.f, a1 = 0.f, a2 = 0.f, a3 = 0.f;
        #pragma unroll
        for (int s = 0; s < NSPLIT; s++) {
            const __nv_bfloat16* Op = d_Opart + ((size_t)(s * BATCH + b) * NTOK + n0 + tok) * ID + d4;
            uint2 v = *(const uint2*)Op;
            __nv_bfloat162 h0 = *reinterpret_cast<__nv_bfloat162*>(&v.x);
            __nv_bfloat162 h1 = *reinterpret_cast<__nv_bfloat162*>(&v.y);
            a0 += __low2float(h0); a1 += __high2float(h0);
            a2 += __low2float(h1); a3 += __high2float(h1);
        }
        sov[tok][d4] = a0; sov[tok][d4 + 1] = a1;
        sov[tok][d4 + 2] = a2; sov[tok][d4 + 3] = a3;
    }
    if (tid < 16) {
        float ls = 0.f;
        #pragma unroll
        for (int s = 0; s < NSPLIT; s++)
            ls += d_lpart[(size_t)(s * BATCH + b) * NTOK + n0 + tid];
        sinv[tid] = 1.f / ls;
    }
    __syncthreads();

    const int tok = tid & 15, cg = tid >> 4;       // 16 channel-groups
    float ov[ID];
    #pragma unroll
    for (int i = 0; i < ID; i++) ov[i] = sov[tok][i];
    const float inv = sinv[tok];
    const int n = n0 + tok;
    const float* xb = x + (size_t)b * CH * NTOK;
    float* ob = out + (size_t)b * CH * NTOK;
    #pragma unroll
    for (int k = 0; k < 4; k++) {
        const int c = cg * 4 + k;
        float acc = 0.f;
        const float* w = &sw[c * ID];
        #pragma unroll
        for (int i = 0; i < ID; i++) acc = fmaf(w[i], ov[i], acc);
        ob[(size_t)c * NTOK + n] = xb[(size_t)c * NTOK + n] + acc * inv * sgate[c];
    }
}

// ---------------- launch ----------------
extern "C" void kernel_launch(void* const* d_in, const int* in_sizes, int n_in,
                              void* d_out, int out_size) {
    const float* x       = (const float*)d_in[0];
    const float* g_w     = (const float*)d_in[1];
    const float* theta_w = (const float*)d_in[2];
    const float* phi_w   = (const float*)d_in[3];
    const float* W_w     = (const float*)d_in[4];
    const float* cg1_w   = (const float*)d_in[5];
    const float* cg1_b   = (const float*)d_in[6];
    const float* cg2_w   = (const float*)d_in[7];
    const float* cg2_b   = (const float*)d_in[8];
    float* out = (float*)d_out;

    pool_kernel<<<BATCH * CH, 256>>>(x);
    proj_kernel<<<dim3(NTOK / 128, BATCH), 512>>>(x, g_w, theta_w, phi_w);
    attn_kernel<<<dim3(NTOK / 128, BATCH * NSPLIT), 128>>>();
    epi_kernel<<<dim3(NTOK / 16, BATCH), 256>>>(x, W_w, cg1_w, cg1_b, cg2_w, cg2_b, out);
}

// round 15
// speedup vs baseline: 1.0121x; 1.0121x over previous
#include <cuda_runtime.h>
#include <cuda_bf16.h>
#include <cstdint>

#define NTOK 9216        // H*W = 96*96
#define BATCH 2
#define CH 64
#define ID 32            // inter dim
#define BOTT 16
#define NSPLIT 4
#define NJ (NTOK / 64 / NSPLIT)   // 36 KV tiles per split

// ---------------- device scratch ----------------
__device__ __align__(16) __nv_bfloat16 d_thetaQ[BATCH * NTOK * ID]; // [B][N][32], pre-scaled
__device__ __align__(16) __nv_bfloat16 d_phiK  [BATCH * NTOK * ID]; // [B][N][32]
__device__ __align__(16) __nv_bfloat16 d_gxT   [BATCH * ID * NTOK]; // [B][32][N]
__device__ __align__(16) __nv_bfloat16 d_Opart[NSPLIT * BATCH * NTOK * ID]; // partial O (bf16)
__device__ float d_lpart[NSPLIT * BATCH * NTOK];                    // partial softmax denom
__device__ float d_pooled[BATCH * CH];

// ---------------- helpers ----------------
// packed bf16x2 cubic fit of 2^x on [-1,1]; bf16 rounding error is common-mode
// between P (numerator) and the HADD2-tree denominator -> largely cancels.
#define C3_BF16X2 0x3D6A3D6Au   // 0.05717
#define C2_BF16X2 0x3E803E80u   // 0.25
#define C1_BF16X2 0x3F313F31u   // 0.69141
#define C0_BF16X2 0x3F803F80u   // 1.0
__device__ __forceinline__ uint32_t exp2_poly_bf16x2(uint32_t x) {
    uint32_t p;
    asm("fma.rn.bf16x2 %0, %1, %2, %3;" : "=r"(p) : "r"(x), "r"(C3_BF16X2), "r"(C2_BF16X2));
    asm("fma.rn.bf16x2 %0, %1, %2, %3;" : "=r"(p) : "r"(p), "r"(x), "r"(C1_BF16X2));
    asm("fma.rn.bf16x2 %0, %1, %2, %3;" : "=r"(p) : "r"(p), "r"(x), "r"(C0_BF16X2));
    return p;
}
__device__ __forceinline__ uint32_t hadd2(uint32_t a, uint32_t b) {
    uint32_t d; asm("add.rn.bf16x2 %0, %1, %2;" : "=r"(d) : "r"(a), "r"(b)); return d;
}
__device__ __forceinline__ float bf16x2_hsum(uint32_t v) {
    __nv_bfloat162 h = *reinterpret_cast<__nv_bfloat162*>(&v);
    return __low2float(h) + __high2float(h);
}
__device__ __forceinline__ uint32_t pack_bf16(float lo, float hi) {
    uint32_t d; asm("cvt.rn.bf16x2.f32 %0, %1, %2;" : "=r"(d) : "f"(hi), "f"(lo)); return d;
}
__device__ __forceinline__ void mma_bf16(float c[4], const uint32_t a[4], uint32_t b0, uint32_t b1) {
    asm volatile(
        "mma.sync.aligned.m16n8k16.row.col.f32.bf16.bf16.f32 "
        "{%0,%1,%2,%3}, {%4,%5,%6,%7}, {%8,%9}, {%0,%1,%2,%3};"
        : "+f"(c[0]), "+f"(c[1]), "+f"(c[2]), "+f"(c[3])
        : "r"(a[0]), "r"(a[1]), "r"(a[2]), "r"(a[3]), "r"(b0), "r"(b1));
}
__device__ __forceinline__ void ldmx4(uint32_t r[4], const __nv_bfloat16* p) {
    uint32_t a = (uint32_t)__cvta_generic_to_shared(p);
    asm volatile("ldmatrix.sync.aligned.m8n8.x4.shared.b16 {%0,%1,%2,%3}, [%4];"
                 : "=r"(r[0]), "=r"(r[1]), "=r"(r[2]), "=r"(r[3]) : "r"(a));
}
__device__ __forceinline__ void cp16(void* smem, const void* gmem) {
    uint32_t s = (uint32_t)__cvta_generic_to_shared(smem);
    asm volatile("cp.async.cg.shared.global [%0], [%1], 16;" :: "r"(s), "l"(gmem));
}
#define CP_COMMIT() asm volatile("cp.async.commit_group;")
#define CP_WAIT0()  asm volatile("cp.async.wait_group 0;")

// ---------------- 1) global average pool ----------------
__global__ void pool_kernel(const float* __restrict__ x) {
    int bc = blockIdx.x;
    const float* p = x + (size_t)bc * NTOK;
    float s = 0.f;
    for (int i = threadIdx.x; i < NTOK; i += 256) s += p[i];
    __shared__ float red[8];
    #pragma unroll
    for (int o = 16; o; o >>= 1) s += __shfl_xor_sync(~0u, s, o);
    if ((threadIdx.x & 31) == 0) red[threadIdx.x >> 5] = s;
    __syncthreads();
    if (threadIdx.x < 8) {
        float v = red[threadIdx.x];
        #pragma unroll
        for (int o = 4; o; o >>= 1) v += __shfl_xor_sync(0xffu, v, o);
        if (threadIdx.x == 0) d_pooled[bc] = v * (1.f / (float)NTOK);
    }
}

// ---------------- 2) projections ----------------
// 512 threads = 4 i-groups x 128 tokens; each thread computes 8 of 32 outputs.
__global__ __launch_bounds__(512) void proj_kernel(const float* __restrict__ x,
                            const float* __restrict__ g_w,
                            const float* __restrict__ theta_w,
                            const float* __restrict__ phi_w) {
    __shared__ float sg[ID * CH], st[ID * CH], sp[ID * CH];
    const int b   = blockIdx.y;
    const int tid = threadIdx.x;
    const int n   = blockIdx.x * 128 + (tid & 127);
    const int ig  = tid >> 7;              // 0..3 -> outputs ig*8 .. ig*8+7
    for (int i = tid; i < ID * CH; i += 512) {
        sg[i] = g_w[i]; st[i] = theta_w[i]; sp[i] = phi_w[i];
    }
    __syncthreads();

    float xv[CH];
    const float* xb = x + (size_t)b * CH * NTOK + n;
    #pragma unroll
    for (int c = 0; c < CH; c++) xv[c] = xb[(size_t)c * NTOK];

    const float qscale = (1.0f / 1.5f) * 1.4426950408889634f; // 1/T * log2(e)

    __nv_bfloat16 tqv[8], pkv[8];
    __nv_bfloat16* gv = d_gxT + (size_t)b * ID * NTOK + n;

    #pragma unroll
    for (int ii = 0; ii < 8; ii++) {
        const int i = ig * 8 + ii;
        float ag = 0.f, at = 0.f, ap = 0.f;
        const float* wg = &sg[i * CH];
        const float* wt = &st[i * CH];
        const float* wp = &sp[i * CH];
        #pragma unroll
        for (int c = 0; c < CH; c++) {
            float xc = xv[c];
            ag = fmaf(wg[c], xc, ag);
            at = fmaf(wt[c], xc, at);
            ap = fmaf(wp[c], xc, ap);
        }
        tqv[ii] = __float2bfloat16(at * qscale);
        pkv[ii] = __float2bfloat16(ap);
        gv[(size_t)i * NTOK] = __float2bfloat16(ag);
    }
    *(uint4*)&d_thetaQ[((size_t)b * NTOK + n) * ID + ig * 8] = *(const uint4*)tqv;
    *(uint4*)&d_phiK  [((size_t)b * NTOK + n) * ID + ig * 8] = *(const uint4*)pkv;
}

// ---------------- 3) flash attention (R8-proven structure) ----------------
// BM=128 (4 warps x 32 rows), BN=64, D=32, KV-split=4, 4 CTAs/SM.
__global__ __launch_bounds__(128, 4) void attn_kernel() {
    const int by    = blockIdx.y;
    const int b     = by / NSPLIT;
    const int split = by % NSPLIT;
    const int j0    = split * NJ;
    const int m0    = blockIdx.x * 128;
    const int tid   = threadIdx.x;
    const int warp  = tid >> 5, lane = tid & 31;
    const int g = lane >> 2, t = lane & 3;
    const int lr = lane & 7, lm = lane >> 3;   // ldmatrix row / matrix-id

    __shared__ __align__(16) __nv_bfloat16 sQ[128][40];
    __shared__ __align__(16) __nv_bfloat16 sK[2][64][40];
    __shared__ __align__(16) __nv_bfloat16 sV[2][32][72];

    const __nv_bfloat16* Qg = d_thetaQ + (size_t)b * NTOK * ID;
    const __nv_bfloat16* Kg = d_phiK   + (size_t)b * NTOK * ID;
    const __nv_bfloat16* Vg = d_gxT    + (size_t)b * ID * NTOK;

    // async-load Q tile [128][32]
    {
        int idx = tid;
        #pragma unroll
        for (int u = 0; u < 4; u++, idx += 128) {
            int r = idx >> 2, c = (idx & 3) * 8;
            cp16(&sQ[r][c], &Qg[(size_t)(m0 + r) * ID + c]);
        }
    }
    // prefetch first K/V tile into buffer 0
    {
        int idx = tid;
        #pragma unroll
        for (int u = 0; u < 2; u++, idx += 128) {
            int r = idx >> 2, c = (idx & 3) * 8;
            cp16(&sK[0][r][c], &Kg[(size_t)(j0 * 64 + r) * ID + c]);
        }
        idx = tid;
        #pragma unroll
        for (int u = 0; u < 2; u++, idx += 128) {
            int r = idx >> 3, c = (idx & 7) * 8;
            cp16(&sV[0][r][c], &Vg[(size_t)r * NTOK + j0 * 64 + c]);
        }
    }
    CP_COMMIT();

    uint32_t qa[2][2][4];      // [m-tile][k-step]
    bool qa_loaded = false;

    float o[2][4][4] = {};     // output d-tiles
    float lacc[2][2] = {};     // per-thread partial softmax denom [mt][row]

    for (int jl = 0; jl < NJ; jl++) {
        const int cur = jl & 1;
        CP_WAIT0();
        __syncthreads();

        if (!qa_loaded) {
            qa_loaded = true;
            #pragma unroll
            for (int mt = 0; mt < 2; mt++)
                #pragma unroll
                for (int ks = 0; ks < 2; ks++)
                    ldmx4(qa[mt][ks],
                          &sQ[warp * 32 + mt * 16 + (lm & 1) * 8 + lr][ks * 16 + (lm >> 1) * 8]);
        }

        // prefetch next tile
        if (jl + 1 < NJ) {
            const int jj = j0 + jl + 1, nb = cur ^ 1;
            int idx = tid;
            #pragma unroll
            for (int u = 0; u < 2; u++, idx += 128) {
                int r = idx >> 2, c = (idx & 3) * 8;
                cp16(&sK[nb][r][c], &Kg[(size_t)(jj * 64 + r) * ID + c]);
            }
            idx = tid;
            #pragma unroll
            for (int u = 0; u < 2; u++, idx += 128) {
                int r = idx >> 3, c = (idx & 7) * 8;
                cp16(&sV[nb][r][c], &Vg[(size_t)r * NTOK + jj * 64 + c]);
            }
        }
        CP_COMMIT();

        // S = Q K^T ; pack logits to bf16x2 per u-tile
        uint32_t pp[2][8][2];
        #pragma unroll
        for (int u = 0; u < 8; u++) {
            uint32_t kb[4];
            ldmx4(kb, &sK[cur][u * 8 + lr][lm * 8]);
            #pragma unroll
            for (int mt = 0; mt < 2; mt++) {
                float s0[4] = {0.f, 0.f, 0.f, 0.f};
                mma_bf16(s0, qa[mt][0], kb[0], kb[1]);
                mma_bf16(s0, qa[mt][1], kb[2], kb[3]);
                pp[mt][u][0] = pack_bf16(s0[0], s0[1]);   // row g
                pp[mt][u][1] = pack_bf16(s0[2], s0[3]);   // row g+8
            }
        }

        // P = 2^S in packed bf16x2
        #pragma unroll
        for (int mt = 0; mt < 2; mt++)
            #pragma unroll
            for (int u = 0; u < 8; u++) {
                pp[mt][u][0] = exp2_poly_bf16x2(pp[mt][u][0]);
                pp[mt][u][1] = exp2_poly_bf16x2(pp[mt][u][1]);
            }

        // denominator: HADD2 tree over packed P, accumulate in f32 per thread
        #pragma unroll
        for (int mt = 0; mt < 2; mt++) {
            #pragma unroll
            for (int r = 0; r < 2; r++) {
                uint32_t a0 = hadd2(pp[mt][0][r], pp[mt][1][r]);
                uint32_t a1 = hadd2(pp[mt][2][r], pp[mt][3][r]);
                uint32_t a2 = hadd2(pp[mt][4][r], pp[mt][5][r]);
                uint32_t a3 = hadd2(pp[mt][6][r], pp[mt][7][r]);
                uint32_t b0 = hadd2(a0, a1);
                uint32_t b1 = hadd2(a2, a3);
                lacc[mt][r] += bf16x2_hsum(b0) + bf16x2_hsum(b1);
            }
        }

        // O += P V
        #pragma unroll
        for (int kk = 0; kk < 4; kk++) {
            #pragma unroll
            for (int dp = 0; dp < 2; dp++) {
                uint32_t vb[4];
                ldmx4(vb, &sV[cur][(dp * 2 + (lm >> 1)) * 8 + lr][kk * 16 + (lm & 1) * 8]);
                #pragma unroll
                for (int mt = 0; mt < 2; mt++) {
                    uint32_t pa[4] = {pp[mt][2 * kk][0], pp[mt][2 * kk][1],
                                      pp[mt][2 * kk + 1][0], pp[mt][2 * kk + 1][1]};
                    mma_bf16(o[mt][dp * 2    ], pa, vb[0], vb[1]);
                    mma_bf16(o[mt][dp * 2 + 1], pa, vb[2], vb[3]);
                }
            }
        }
    }

    // reduce l across the 4 lanes of each row-quad (once)
    #pragma unroll
    for (int mt = 0; mt < 2; mt++)
        #pragma unroll
        for (int r = 0; r < 2; r++) {
            lacc[mt][r] += __shfl_xor_sync(~0u, lacc[mt][r], 1);
            lacc[mt][r] += __shfl_xor_sync(~0u, lacc[mt][r], 2);
        }

    const size_t pbase = (size_t)(split * BATCH + b) * NTOK;
    __nv_bfloat16* Op = d_Opart + pbase * ID;
    #pragma unroll
    for (int mt = 0; mt < 2; mt++) {
        int r0 = m0 + warp * 32 + mt * 16 + g;
        if (t == 0) {
            d_lpart[pbase + r0]     = lacc[mt][0];
            d_lpart[pbase + r0 + 8] = lacc[mt][1];
        }
        #pragma unroll
        for (int dt = 0; dt < 4; dt++) {
            int c = dt * 8 + 2 * t;
            *(uint32_t*)&Op[(size_t)r0 * ID + c]       = pack_bf16(o[mt][dt][0], o[mt][dt][1]);
            *(uint32_t*)&Op[(size_t)(r0 + 8) * ID + c] = pack_bf16(o[mt][dt][2], o[mt][dt][3]);
        }
    }
}

// ---------------- 4) epilogue: gate MLP + combine splits + out ----------------
// 512 threads, 64 tokens/block (grid 288): low fixed cost per block (one W_w
// load, one gate MLP) with 8 channel-groups -> only 8 channels per thread.
__global__ __launch_bounds__(512) void epi_kernel(const float* __restrict__ x, const float* __restrict__ W_w,
                           const float* __restrict__ cg1_w, const float* __restrict__ cg1_b,
                           const float* __restrict__ cg2_w, const float* __restrict__ cg2_b,
                           float* __restrict__ out) {
    __shared__ float sw[CH * ID];
    __shared__ float sov[64][33];     // odd pitch: conflict-free column reads
    __shared__ float sinv[64];
    __shared__ float sh[BOTT];
    __shared__ float sgate[CH];
    const int b   = blockIdx.y;
    const int n0  = blockIdx.x * 64;
    const int tid = threadIdx.x;

    for (int i = tid; i < CH * ID; i += 512) sw[i] = W_w[i];
    if (tid < BOTT) {
        float acc = cg1_b[tid];
        #pragma unroll
        for (int c = 0; c < CH; c++) acc = fmaf(d_pooled[b * CH + c], cg1_w[tid * CH + c], acc);
        sh[tid] = fmaxf(acc, 0.f);
    }
    // combine splits: 64 tokens x 8 dim-quads = 512 items, exactly 1/thread
    {
        const int tok = tid >> 3, d4 = (tid & 7) * 4;
        float a0 = 0.f, a1 = 0.f, a2 = 0.f, a3 = 0.f;
        #pragma unroll
        for (int s = 0; s < NSPLIT; s++) {
            const __nv_bfloat16* Op = d_Opart + ((size_t)(s * BATCH + b) * NTOK + n0 + tok) * ID + d4;
            uint2 v = *(const uint2*)Op;
            __nv_bfloat162 h0 = *reinterpret_cast<__nv_bfloat162*>(&v.x);
            __nv_bfloat162 h1 = *reinterpret_cast<__nv_bfloat162*>(&v.y);
            a0 += __low2float(h0); a1 += __high2float(h0);
            a2 += __low2float(h1); a3 += __high2float(h1);
        }
        sov[tok][d4] = a0; sov[tok][d4 + 1] = a1;
        sov[tok][d4 + 2] = a2; sov[tok][d4 + 3] = a3;
    }
    if (tid < 64) {
        float ls = 0.f;
        #pragma unroll
        for (int s = 0; s < NSPLIT; s++)
            ls += d_lpart[(size_t)(s * BATCH + b) * NTOK + n0 + tid];
        sinv[tid] = 1.f / ls;
    }
    __syncthreads();
    if (tid < CH) {
        float acc = cg2_b[tid];
        #pragma unroll
        for (int k = 0; k < BOTT; k++) acc = fmaf(sh[k], cg2_w[tid * BOTT + k], acc);
        sgate[tid] = 0.8f / (1.f + __expf(-acc));
    }
    __syncthreads();

    const int tok = tid & 63, cg = tid >> 6;       // 8 channel-groups
    float ov[ID];
    #pragma unroll
    for (int i = 0; i < ID; i++) ov[i] = sov[tok][i];
    const float inv = sinv[tok];
    const int n = n0 + tok;
    const float* xb = x + (size_t)b * CH * NTOK;
    float* ob = out + (size_t)b * CH * NTOK;
    #pragma unroll
    for (int k = 0; k < 8; k++) {
        const int c = cg * 8 + k;
        float acc = 0.f;
        const float* w = &sw[c * ID];
        #pragma unroll
        for (int i = 0; i < ID; i++) acc = fmaf(w[i], ov[i], acc);
        ob[(size_t)c * NTOK + n] = xb[(size_t)c * NTOK + n] + acc * inv * sgate[c];
    }
}

// ---------------- launch ----------------
extern "C" void kernel_launch(void* const* d_in, const int* in_sizes, int n_in,
                              void* d_out, int out_size) {
    const float* x       = (const float*)d_in[0];
    const float* g_w     = (const float*)d_in[1];
    const float* theta_w = (const float*)d_in[2];
    const float* phi_w   = (const float*)d_in[3];
    const float* W_w     = (const float*)d_in[4];
    const float* cg1_w   = (const float*)d_in[5];
    const float* cg1_b   = (const float*)d_in[6];
    const float* cg2_w   = (const float*)d_in[7];
    const float* cg2_b   = (const float*)d_in[8];
    float* out = (float*)d_out;

    pool_kernel<<<BATCH * CH, 256>>>(x);
    proj_kernel<<<dim3(NTOK / 128, BATCH), 512>>>(x, g_w, theta_w, phi_w);
    attn_kernel<<<dim3(NTOK / 128, BATCH * NSPLIT), 128>>>();
    epi_kernel<<<dim3(NTOK / 64, BATCH), 512>>>(x, W_w, cg1_w, cg1_b, cg2_w, cg2_b, out);
}

// round 16
// speedup vs baseline: 1.0704x; 1.0576x over previous
#include <cuda_runtime.h>
#include <cuda_bf16.h>
#include <cstdint>

#define NTOK 9216        // H*W = 96*96
#define BATCH 2
#define CH 64
#define ID 32            // inter dim
#define BOTT 16
#define NSPLIT 4
#define NJ (NTOK / 64 / NSPLIT)   // 36 KV tiles per split

// ---------------- device scratch ----------------
__device__ __align__(16) __nv_bfloat16 d_thetaQ[BATCH * NTOK * ID]; // [B][N][32], pre-scaled
__device__ __align__(16) __nv_bfloat16 d_phiK  [BATCH * NTOK * ID]; // [B][N][32]
__device__ __align__(16) __nv_bfloat16 d_gxT   [BATCH * ID * NTOK]; // [B][32][N]
__device__ __align__(16) float d_Opart[NSPLIT * BATCH * NTOK * ID]; // partial O (f32, R8-proven)
__device__ float d_lpart[NSPLIT * BATCH * NTOK];                    // partial softmax denom
__device__ float d_pooled[BATCH * CH];

// ---------------- helpers ----------------
// packed bf16x2 cubic fit of 2^x on [-1,1]; bf16 rounding error is common-mode
// between P (numerator) and the HADD2-tree denominator -> largely cancels.
#define C3_BF16X2 0x3D6A3D6Au   // 0.05717
#define C2_BF16X2 0x3E803E80u   // 0.25
#define C1_BF16X2 0x3F313F31u   // 0.69141
#define C0_BF16X2 0x3F803F80u   // 1.0
__device__ __forceinline__ uint32_t exp2_poly_bf16x2(uint32_t x) {
    uint32_t p;
    asm("fma.rn.bf16x2 %0, %1, %2, %3;" : "=r"(p) : "r"(x), "r"(C3_BF16X2), "r"(C2_BF16X2));
    asm("fma.rn.bf16x2 %0, %1, %2, %3;" : "=r"(p) : "r"(p), "r"(x), "r"(C1_BF16X2));
    asm("fma.rn.bf16x2 %0, %1, %2, %3;" : "=r"(p) : "r"(p), "r"(x), "r"(C0_BF16X2));
    return p;
}
__device__ __forceinline__ uint32_t hadd2(uint32_t a, uint32_t b) {
    uint32_t d; asm("add.rn.bf16x2 %0, %1, %2;" : "=r"(d) : "r"(a), "r"(b)); return d;
}
__device__ __forceinline__ float bf16x2_hsum(uint32_t v) {
    __nv_bfloat162 h = *reinterpret_cast<__nv_bfloat162*>(&v);
    return __low2float(h) + __high2float(h);
}
__device__ __forceinline__ uint32_t pack_bf16(float lo, float hi) {
    uint32_t d; asm("cvt.rn.bf16x2.f32 %0, %1, %2;" : "=r"(d) : "f"(hi), "f"(lo)); return d;
}
__device__ __forceinline__ void mma_bf16(float c[4], const uint32_t a[4], uint32_t b0, uint32_t b1) {
    asm volatile(
        "mma.sync.aligned.m16n8k16.row.col.f32.bf16.bf16.f32 "
        "{%0,%1,%2,%3}, {%4,%5,%6,%7}, {%8,%9}, {%0,%1,%2,%3};"
        : "+f"(c[0]), "+f"(c[1]), "+f"(c[2]), "+f"(c[3])
        : "r"(a[0]), "r"(a[1]), "r"(a[2]), "r"(a[3]), "r"(b0), "r"(b1));
}
__device__ __forceinline__ void ldmx4(uint32_t r[4], const __nv_bfloat16* p) {
    uint32_t a = (uint32_t)__cvta_generic_to_shared(p);
    asm volatile("ldmatrix.sync.aligned.m8n8.x4.shared.b16 {%0,%1,%2,%3}, [%4];"
                 : "=r"(r[0]), "=r"(r[1]), "=r"(r[2]), "=r"(r[3]) : "r"(a));
}
__device__ __forceinline__ void cp16(void* smem, const void* gmem) {
    uint32_t s = (uint32_t)__cvta_generic_to_shared(smem);
    asm volatile("cp.async.cg.shared.global [%0], [%1], 16;" :: "r"(s), "l"(gmem));
}
#define CP_COMMIT() asm volatile("cp.async.commit_group;")
#define CP_WAIT0()  asm volatile("cp.async.wait_group 0;")

// ---------------- 1) global average pool ----------------
__global__ void pool_kernel(const float* __restrict__ x) {
    int bc = blockIdx.x;
    const float* p = x + (size_t)bc * NTOK;
    float s = 0.f;
    for (int i = threadIdx.x; i < NTOK; i += 256) s += p[i];
    __shared__ float red[8];
    #pragma unroll
    for (int o = 16; o; o >>= 1) s += __shfl_xor_sync(~0u, s, o);
    if ((threadIdx.x & 31) == 0) red[threadIdx.x >> 5] = s;
    __syncthreads();
    if (threadIdx.x < 8) {
        float v = red[threadIdx.x];
        #pragma unroll
        for (int o = 4; o; o >>= 1) v += __shfl_xor_sync(0xffu, v, o);
        if (threadIdx.x == 0) d_pooled[bc] = v * (1.f / (float)NTOK);
    }
}

// ---------------- 2) projections ----------------
// 512 threads = 4 i-groups x 128 tokens; each thread computes 8 of 32 outputs.
__global__ __launch_bounds__(512) void proj_kernel(const float* __restrict__ x,
                            const float* __restrict__ g_w,
                            const float* __restrict__ theta_w,
                            const float* __restrict__ phi_w) {
    __shared__ float sg[ID * CH], st[ID * CH], sp[ID * CH];
    const int b   = blockIdx.y;
    const int tid = threadIdx.x;
    const int n   = blockIdx.x * 128 + (tid & 127);
    const int ig  = tid >> 7;              // 0..3 -> outputs ig*8 .. ig*8+7
    for (int i = tid; i < ID * CH; i += 512) {
        sg[i] = g_w[i]; st[i] = theta_w[i]; sp[i] = phi_w[i];
    }
    __syncthreads();

    float xv[CH];
    const float* xb = x + (size_t)b * CH * NTOK + n;
    #pragma unroll
    for (int c = 0; c < CH; c++) xv[c] = xb[(size_t)c * NTOK];

    const float qscale = (1.0f / 1.5f) * 1.4426950408889634f; // 1/T * log2(e)

    __nv_bfloat16 tqv[8], pkv[8];
    __nv_bfloat16* gv = d_gxT + (size_t)b * ID * NTOK + n;

    #pragma unroll
    for (int ii = 0; ii < 8; ii++) {
        const int i = ig * 8 + ii;
        float ag = 0.f, at = 0.f, ap = 0.f;
        const float* wg = &sg[i * CH];
        const float* wt = &st[i * CH];
        const float* wp = &sp[i * CH];
        #pragma unroll
        for (int c = 0; c < CH; c++) {
            float xc = xv[c];
            ag = fmaf(wg[c], xc, ag);
            at = fmaf(wt[c], xc, at);
            ap = fmaf(wp[c], xc, ap);
        }
        tqv[ii] = __float2bfloat16(at * qscale);
        pkv[ii] = __float2bfloat16(ap);
        gv[(size_t)i * NTOK] = __float2bfloat16(ag);
    }
    *(uint4*)&d_thetaQ[((size_t)b * NTOK + n) * ID + ig * 8] = *(const uint4*)tqv;
    *(uint4*)&d_phiK  [((size_t)b * NTOK + n) * ID + ig * 8] = *(const uint4*)pkv;
}

// ---------------- 3) flash attention (R8 byte-for-byte) ----------------
// BM=128 (4 warps x 32 rows), BN=64, D=32, KV-split=4, 4 CTAs/SM.
__global__ __launch_bounds__(128, 4) void attn_kernel() {
    const int by    = blockIdx.y;
    const int b     = by / NSPLIT;
    const int split = by % NSPLIT;
    const int j0    = split * NJ;
    const int m0    = blockIdx.x * 128;
    const int tid   = threadIdx.x;
    const int warp  = tid >> 5, lane = tid & 31;
    const int g = lane >> 2, t = lane & 3;
    const int lr = lane & 7, lm = lane >> 3;   // ldmatrix row / matrix-id

    __shared__ __align__(16) __nv_bfloat16 sQ[128][40];
    __shared__ __align__(16) __nv_bfloat16 sK[2][64][40];
    __shared__ __align__(16) __nv_bfloat16 sV[2][32][72];

    const __nv_bfloat16* Qg = d_thetaQ + (size_t)b * NTOK * ID;
    const __nv_bfloat16* Kg = d_phiK   + (size_t)b * NTOK * ID;
    const __nv_bfloat16* Vg = d_gxT    + (size_t)b * ID * NTOK;

    // async-load Q tile [128][32]
    {
        int idx = tid;
        #pragma unroll
        for (int u = 0; u < 4; u++, idx += 128) {
            int r = idx >> 2, c = (idx & 3) * 8;
            cp16(&sQ[r][c], &Qg[(size_t)(m0 + r) * ID + c]);
        }
    }
    // prefetch first K/V tile into buffer 0
    {
        int idx = tid;
        #pragma unroll
        for (int u = 0; u < 2; u++, idx += 128) {
            int r = idx >> 2, c = (idx & 3) * 8;
            cp16(&sK[0][r][c], &Kg[(size_t)(j0 * 64 + r) * ID + c]);
        }
        idx = tid;
        #pragma unroll
        for (int u = 0; u < 2; u++, idx += 128) {
            int r = idx >> 3, c = (idx & 7) * 8;
            cp16(&sV[0][r][c], &Vg[(size_t)r * NTOK + j0 * 64 + c]);
        }
    }
    CP_COMMIT();

    uint32_t qa[2][2][4];      // [m-tile][k-step]
    bool qa_loaded = false;

    float o[2][4][4] = {};     // output d-tiles
    float lacc[2][2] = {};     // per-thread partial softmax denom [mt][row]

    for (int jl = 0; jl < NJ; jl++) {
        const int cur = jl & 1;
        CP_WAIT0();
        __syncthreads();

        if (!qa_loaded) {
            qa_loaded = true;
            #pragma unroll
            for (int mt = 0; mt < 2; mt++)
                #pragma unroll
                for (int ks = 0; ks < 2; ks++)
                    ldmx4(qa[mt][ks],
                          &sQ[warp * 32 + mt * 16 + (lm & 1) * 8 + lr][ks * 16 + (lm >> 1) * 8]);
        }

        // prefetch next tile
        if (jl + 1 < NJ) {
            const int jj = j0 + jl + 1, nb = cur ^ 1;
            int idx = tid;
            #pragma unroll
            for (int u = 0; u < 2; u++, idx += 128) {
                int r = idx >> 2, c = (idx & 3) * 8;
                cp16(&sK[nb][r][c], &Kg[(size_t)(jj * 64 + r) * ID + c]);
            }
            idx = tid;
            #pragma unroll
            for (int u = 0; u < 2; u++, idx += 128) {
                int r = idx >> 3, c = (idx & 7) * 8;
                cp16(&sV[nb][r][c], &Vg[(size_t)r * NTOK + jj * 64 + c]);
            }
        }
        CP_COMMIT();

        // S = Q K^T ; pack logits to bf16x2 per u-tile
        uint32_t pp[2][8][2];
        #pragma unroll
        for (int u = 0; u < 8; u++) {
            uint32_t kb[4];
            ldmx4(kb, &sK[cur][u * 8 + lr][lm * 8]);
            #pragma unroll
            for (int mt = 0; mt < 2; mt++) {
                float s0[4] = {0.f, 0.f, 0.f, 0.f};
                mma_bf16(s0, qa[mt][0], kb[0], kb[1]);
                mma_bf16(s0, qa[mt][1], kb[2], kb[3]);
                pp[mt][u][0] = pack_bf16(s0[0], s0[1]);   // row g
                pp[mt][u][1] = pack_bf16(s0[2], s0[3]);   // row g+8
            }
        }

        // P = 2^S in packed bf16x2
        #pragma unroll
        for (int mt = 0; mt < 2; mt++)
            #pragma unroll
            for (int u = 0; u < 8; u++) {
                pp[mt][u][0] = exp2_poly_bf16x2(pp[mt][u][0]);
                pp[mt][u][1] = exp2_poly_bf16x2(pp[mt][u][1]);
            }

        // denominator: HADD2 tree over packed P, accumulate in f32 per thread
        #pragma unroll
        for (int mt = 0; mt < 2; mt++) {
            #pragma unroll
            for (int r = 0; r < 2; r++) {
                uint32_t a0 = hadd2(pp[mt][0][r], pp[mt][1][r]);
                uint32_t a1 = hadd2(pp[mt][2][r], pp[mt][3][r]);
                uint32_t a2 = hadd2(pp[mt][4][r], pp[mt][5][r]);
                uint32_t a3 = hadd2(pp[mt][6][r], pp[mt][7][r]);
                uint32_t b0 = hadd2(a0, a1);
                uint32_t b1 = hadd2(a2, a3);
                lacc[mt][r] += bf16x2_hsum(b0) + bf16x2_hsum(b1);
            }
        }

        // O += P V
        #pragma unroll
        for (int kk = 0; kk < 4; kk++) {
            #pragma unroll
            for (int dp = 0; dp < 2; dp++) {
                uint32_t vb[4];
                ldmx4(vb, &sV[cur][(dp * 2 + (lm >> 1)) * 8 + lr][kk * 16 + (lm & 1) * 8]);
                #pragma unroll
                for (int mt = 0; mt < 2; mt++) {
                    uint32_t pa[4] = {pp[mt][2 * kk][0], pp[mt][2 * kk][1],
                                      pp[mt][2 * kk + 1][0], pp[mt][2 * kk + 1][1]};
                    mma_bf16(o[mt][dp * 2    ], pa, vb[0], vb[1]);
                    mma_bf16(o[mt][dp * 2 + 1], pa, vb[2], vb[3]);
                }
            }
        }
    }

    // reduce l across the 4 lanes of each row-quad (once)
    #pragma unroll
    for (int mt = 0; mt < 2; mt++)
        #pragma unroll
        for (int r = 0; r < 2; r++) {
            lacc[mt][r] += __shfl_xor_sync(~0u, lacc[mt][r], 1);
            lacc[mt][r] += __shfl_xor_sync(~0u, lacc[mt][r], 2);
        }

    const size_t pbase = (size_t)(split * BATCH + b) * NTOK;
    float* Op = d_Opart + pbase * ID;
    #pragma unroll
    for (int mt = 0; mt < 2; mt++) {
        int r0 = m0 + warp * 32 + mt * 16 + g;
        if (t == 0) {
            d_lpart[pbase + r0]     = lacc[mt][0];
            d_lpart[pbase + r0 + 8] = lacc[mt][1];
        }
        #pragma unroll
        for (int dt = 0; dt < 4; dt++) {
            int c = dt * 8 + 2 * t;
            *(float2*)&Op[(size_t)r0 * ID + c]       = make_float2(o[mt][dt][0], o[mt][dt][1]);
            *(float2*)&Op[(size_t)(r0 + 8) * ID + c] = make_float2(o[mt][dt][2], o[mt][dt][3]);
        }
    }
}

// ---------------- 4) epilogue: gate MLP + combine splits + out ----------------
// 512 threads, 64 tokens/block (grid 288): low fixed cost per block (one W_w
// load, one gate MLP) with 8 channel-groups -> only 8 channels per thread.
__global__ __launch_bounds__(512) void epi_kernel(const float* __restrict__ x, const float* __restrict__ W_w,
                           const float* __restrict__ cg1_w, const float* __restrict__ cg1_b,
                           const float* __restrict__ cg2_w, const float* __restrict__ cg2_b,
                           float* __restrict__ out) {
    __shared__ float sw[CH * ID];
    __shared__ float sov[64][33];     // odd pitch: conflict-free column reads
    __shared__ float sinv[64];
    __shared__ float sh[BOTT];
    __shared__ float sgate[CH];
    const int b   = blockIdx.y;
    const int n0  = blockIdx.x * 64;
    const int tid = threadIdx.x;

    for (int i = tid; i < CH * ID; i += 512) sw[i] = W_w[i];
    if (tid < BOTT) {
        float acc = cg1_b[tid];
        #pragma unroll
        for (int c = 0; c < CH; c++) acc = fmaf(d_pooled[b * CH + c], cg1_w[tid * CH + c], acc);
        sh[tid] = fmaxf(acc, 0.f);
    }
    // combine splits: 64 tokens x 8 dim-quads = 512 items, exactly 1/thread
    {
        const int tok = tid >> 3, d4 = (tid & 7) * 4;
        float4 acc = make_float4(0.f, 0.f, 0.f, 0.f);
        #pragma unroll
        for (int s = 0; s < NSPLIT; s++) {
            const float4 v = *(const float4*)&d_Opart[((size_t)(s * BATCH + b) * NTOK + n0 + tok) * ID + d4];
            acc.x += v.x; acc.y += v.y; acc.z += v.z; acc.w += v.w;
        }
        sov[tok][d4]     = acc.x; sov[tok][d4 + 1] = acc.y;
        sov[tok][d4 + 2] = acc.z; sov[tok][d4 + 3] = acc.w;
    }
    if (tid < 64) {
        float ls = 0.f;
        #pragma unroll
        for (int s = 0; s < NSPLIT; s++)
            ls += d_lpart[(size_t)(s * BATCH + b) * NTOK + n0 + tid];
        sinv[tid] = 1.f / ls;
    }
    __syncthreads();
    if (tid < CH) {
        float acc = cg2_b[tid];
        #pragma unroll
        for (int k = 0; k < BOTT; k++) acc = fmaf(sh[k], cg2_w[tid * BOTT + k], acc);
        sgate[tid] = 0.8f / (1.f + __expf(-acc));
    }
    __syncthreads();

    const int tok = tid & 63, cg = tid >> 6;       // 8 channel-groups
    float ov[ID];
    #pragma unroll
    for (int i = 0; i < ID; i++) ov[i] = sov[tok][i];
    const float inv = sinv[tok];
    const int n = n0 + tok;
    const float* xb = x + (size_t)b * CH * NTOK;
    float* ob = out + (size_t)b * CH * NTOK;
    #pragma unroll
    for (int k = 0; k < 8; k++) {
        const int c = cg * 8 + k;
        float acc = 0.f;
        const float* w = &sw[c * ID];
        #pragma unroll
        for (int i = 0; i < ID; i++) acc = fmaf(w[i], ov[i], acc);
        ob[(size_t)c * NTOK + n] = xb[(size_t)c * NTOK + n] + acc * inv * sgate[c];
    }
}

// ---------------- launch ----------------
extern "C" void kernel_launch(void* const* d_in, const int* in_sizes, int n_in,
                              void* d_out, int out_size) {
    const float* x       = (const float*)d_in[0];
    const float* g_w     = (const float*)d_in[1];
    const float* theta_w = (const float*)d_in[2];
    const float* phi_w   = (const float*)d_in[3];
    const float* W_w     = (const float*)d_in[4];
    const float* cg1_w   = (const float*)d_in[5];
    const float* cg1_b   = (const float*)d_in[6];
    const float* cg2_w   = (const float*)d_in[7];
    const float* cg2_b   = (const float*)d_in[8];
    float* out = (float*)d_out;

    pool_kernel<<<BATCH * CH, 256>>>(x);
    proj_kernel<<<dim3(NTOK / 128, BATCH), 512>>>(x, g_w, theta_w, phi_w);
    attn_kernel<<<dim3(NTOK / 128, BATCH * NSPLIT), 128>>>();
    epi_kernel<<<dim3(NTOK / 64, BATCH), 512>>>(x, W_w, cg1_w, cg1_b, cg2_w, cg2_b, out);
}